// round 8
// baseline (speedup 1.0000x reference)
#include <cuda_runtime.h>
#include <cuda_bf16.h>
#include <math.h>

// ---------------- problem constants ----------------
#define Bb   2
#define Ss   1024
#define Dm   2560
#define Hh   32
#define HD   80
#define BS   32
#define NBLK 32
#define KTOP 16
#define BH   (Bb*Hh)          // 64
#define ROWS (Bb*Ss)          // 2048
#define SCALE 0.11180339887498949f   // 80^-0.5

#define ACT_NONE 0
#define ACT_GELU 1

// ---------------- scratch (static device globals; no allocations) ------------
__device__ float    g_q[ROWS*Dm];
__device__ float    g_k[ROWS*Dm];
__device__ float    g_v[ROWS*Dm];
__device__ float    g_gh[ROWS*(Dm/2)];
__device__ float    g_gates[ROWS*3];
__device__ float    g_tb[2*BH*NBLK*Dm];        // [4096, 2560]
__device__ float    g_h1[2*BH*NBLK*320];       // [4096, 320]
__device__ float    g_kcvc[2*BH*NBLK*HD];      // kc rows 0..2047, vc rows 2048..4095
__device__ float    g_scores[(size_t)BH*Ss*Ss];// 268 MB
__device__ unsigned g_mask[BH*Ss];
__device__ float    g_comb[ROWS*Dm];

__device__ __forceinline__ float gelu_exact(float x) {
    return 0.5f * x * (1.0f + erff(x * 0.70710678118654752440f));
}

// =====================================================================
// SIMT fp32 GEMM (Wq, Wk) — register-staged prefetch + double-buffered
// smem. The per-output fmaf chain over ascending k is UNCHANGED ->
// bit-identical to the validated numerics.
// Requires M%128==0, N%128==0, K%16==0.
// =====================================================================
__global__ void __launch_bounds__(256)
gemm_f32_v2(const float* __restrict__ A, const float* __restrict__ B,
            const float* __restrict__ bias, float* __restrict__ C,
            int M, int N, int K, int act)
{
    __shared__ float As[2][16][132];   // [buf][k][m]
    __shared__ float Bs[2][16][132];   // [buf][k][n]
    const int tid = threadIdx.x;
    const int tx = tid & 15, ty = tid >> 4;
    const int m0 = blockIdx.y * 128, n0 = blockIdx.x * 128;

    const int am = (tid * 2) >> 2;           // rows for A loads (2 per thread)
    const int ak4 = ((tid * 2) & 3) * 4;
    const int bk = (tid * 2) >> 5;
    const int bn4 = ((tid * 2) & 31) * 4;

    float4 pa[2], pb[2];

    // prologue: load tile 0
    #pragma unroll
    for (int r = 0; r < 2; r++) {
        int idx = r * 256 + tid;
        int m = idx >> 2, k4 = (idx & 3) * 4;
        pa[r] = *reinterpret_cast<const float4*>(&A[(size_t)(m0 + m) * K + k4]);
        int k = idx >> 5, n4 = (idx & 31) * 4;
        pb[r] = *reinterpret_cast<const float4*>(&B[(size_t)k * N + n0 + n4]);
    }
    {
        #pragma unroll
        for (int r = 0; r < 2; r++) {
            int idx = r * 256 + tid;
            int m = idx >> 2, k4 = (idx & 3) * 4;
            As[0][k4 + 0][m] = pa[r].x;
            As[0][k4 + 1][m] = pa[r].y;
            As[0][k4 + 2][m] = pa[r].z;
            As[0][k4 + 3][m] = pa[r].w;
            int k = idx >> 5, n4 = (idx & 31) * 4;
            *reinterpret_cast<float4*>(&Bs[0][k][n4]) = pb[r];
        }
    }
    __syncthreads();

    float acc[8][8] = {};
    int buf = 0;

    for (int k0 = 0; k0 < K; k0 += 16) {
        const bool nxt = (k0 + 16) < K;
        if (nxt) {
            #pragma unroll
            for (int r = 0; r < 2; r++) {
                int idx = r * 256 + tid;
                int m = idx >> 2, k4 = (idx & 3) * 4;
                pa[r] = *reinterpret_cast<const float4*>(&A[(size_t)(m0 + m) * K + k0 + 16 + k4]);
                int k = idx >> 5, n4 = (idx & 31) * 4;
                pb[r] = *reinterpret_cast<const float4*>(&B[(size_t)(k0 + 16 + k) * N + n0 + n4]);
            }
        }

        #pragma unroll
        for (int kk = 0; kk < 16; kk++) {
            float a[8], b[8];
            *reinterpret_cast<float4*>(&a[0]) = *reinterpret_cast<const float4*>(&As[buf][kk][ty * 4]);
            *reinterpret_cast<float4*>(&a[4]) = *reinterpret_cast<const float4*>(&As[buf][kk][64 + ty * 4]);
            *reinterpret_cast<float4*>(&b[0]) = *reinterpret_cast<const float4*>(&Bs[buf][kk][tx * 4]);
            *reinterpret_cast<float4*>(&b[4]) = *reinterpret_cast<const float4*>(&Bs[buf][kk][64 + tx * 4]);
            #pragma unroll
            for (int i = 0; i < 8; i++)
                #pragma unroll
                for (int j = 0; j < 8; j++)
                    acc[i][j] = fmaf(a[i], b[j], acc[i][j]);
        }

        if (nxt) {
            int nb = buf ^ 1;
            #pragma unroll
            for (int r = 0; r < 2; r++) {
                int idx = r * 256 + tid;
                int m = idx >> 2, k4 = (idx & 3) * 4;
                As[nb][k4 + 0][m] = pa[r].x;
                As[nb][k4 + 1][m] = pa[r].y;
                As[nb][k4 + 2][m] = pa[r].z;
                As[nb][k4 + 3][m] = pa[r].w;
                int k = idx >> 5, n4 = (idx & 31) * 4;
                *reinterpret_cast<float4*>(&Bs[nb][k][n4]) = pb[r];
            }
            __syncthreads();
            buf = nb;
        }
    }

    #pragma unroll
    for (int i = 0; i < 8; i++) {
        int row = m0 + ((i < 4) ? (ty * 4 + i) : (64 + ty * 4 + i - 4));
        #pragma unroll
        for (int jg = 0; jg < 2; jg++) {
            int col = n0 + jg * 64 + tx * 4;
            float4 o;
            float* oc = &o.x;
            #pragma unroll
            for (int jj = 0; jj < 4; jj++) {
                float v = acc[i][jg * 4 + jj] + bias[col + jj];
                if (act == ACT_GELU) v = gelu_exact(v);
                oc[jj] = v;
            }
            *reinterpret_cast<float4*>(&C[(size_t)row * N + col]) = o;
        }
    }
}

// ---------------- ROUND-1 batched NT GEMM: scores = SCALE * Q Kᵀ -------------
__global__ void scores_kernel(const float* __restrict__ q, const float* __restrict__ k,
                              float* __restrict__ scores)
{
    int bh = blockIdx.z;
    int b = bh >> 5, h = bh & 31;
    int i0 = blockIdx.y * 64, j0 = blockIdx.x * 64;
    __shared__ float Qs[64][81];
    __shared__ float Ks[64][81];
    int tx = threadIdx.x, ty = threadIdx.y, tid = ty * 16 + tx;

    for (int e = tid; e < 64 * 80; e += 256) {
        int r = e / 80, c = e % 80;
        Qs[r][c] = q[((size_t)(b * Ss + i0 + r)) * Dm + h * HD + c];
        Ks[r][c] = k[((size_t)(b * Ss + j0 + r)) * Dm + h * HD + c];
    }
    __syncthreads();

    float acc[4][4] = {};
    #pragma unroll 8
    for (int kk = 0; kk < 80; kk++) {
        float a[4], bb[4];
        #pragma unroll
        for (int i = 0; i < 4; i++) a[i] = Qs[ty * 4 + i][kk];
        #pragma unroll
        for (int j = 0; j < 4; j++) bb[j] = Ks[tx * 4 + j][kk];
        #pragma unroll
        for (int i = 0; i < 4; i++)
            #pragma unroll
            for (int j = 0; j < 4; j++)
                acc[i][j] = fmaf(a[i], bb[j], acc[i][j]);
    }
    #pragma unroll
    for (int i = 0; i < 4; i++)
        #pragma unroll
        for (int j = 0; j < 4; j++)
            scores[((size_t)bh * Ss + i0 + ty * 4 + i) * Ss + j0 + tx * 4 + j] =
                acc[i][j] * SCALE;
}

// =====================================================================
// 3xTF32 tensor-core GEMM with register-staged prefetch (NN only):
//   C = act(alpha * A@B + bias) [+ Cprev]
//   Raw fp32 smem (conflict-free); hi/lo split at fragment load.
//   Prefetch next tile's LDGs before compute; single smem buffer with
//   two barriers per iteration (smem too big to double).
// =====================================================================
__device__ __forceinline__ unsigned f2tf32(float x) {
    unsigned u;
    asm("cvt.rna.tf32.f32 %0, %1;" : "=r"(u) : "f"(x));
    return u;
}

__device__ __forceinline__ void tf32_split2(float x, unsigned& hi, unsigned& lo) {
    hi = f2tf32(x);
    lo = f2tf32(x - __uint_as_float(hi));
}

#define MMA_TF32(C, Ar, Br)                                              \
    asm volatile(                                                        \
        "mma.sync.aligned.m16n8k8.row.col.f32.tf32.tf32.f32 "            \
        "{%0,%1,%2,%3},{%4,%5,%6,%7},{%8,%9},{%0,%1,%2,%3};"             \
        : "+f"(C[0]), "+f"(C[1]), "+f"(C[2]), "+f"(C[3])                 \
        : "r"(Ar[0]), "r"(Ar[1]), "r"(Ar[2]), "r"(Ar[3]),                \
          "r"(Br[0]), "r"(Br[1]))

template<bool BETA1>
__global__ void __launch_bounds__(256)
mma_gemm(const float* __restrict__ A, const float* __restrict__ B,
         const float* __restrict__ bias, float* __restrict__ C,
         int M, int N, int K, int lda, int ldb, int ldc,
         long long sAz, long long sAb, long long sBz, long long sBb,
         long long sCz, long long sCb, float alpha, int act)
{
    __shared__ float Asm[128 * 36];                 // A: [m][k], stride 36
    __shared__ float Bsm[32 * 136];                 // B: [k][n], stride 136

    const int z = blockIdx.z;
    const float* Ap = A + (size_t)z * sAz + (size_t)(z >> 5) * sAb;
    const float* Bp = B + (size_t)z * sBz + (size_t)(z >> 5) * sBb;
    float*       Cp = C + (size_t)z * sCz + (size_t)(z >> 5) * sCb;

    const int m0 = blockIdx.y * 128, n0 = blockIdx.x * 128;
    const int tid  = threadIdx.x;
    const int warp = tid >> 5, lane = tid & 31;
    const int wm = warp & 1, wn = warp >> 1;          // 2 x 4 warps
    const int mBase = wm * 64, nBase = wn * 32;
    const int lr = lane >> 2, lc = lane & 3;

    float4 pa[4], pb[4];

    // prologue: load + store tile 0
    #pragma unroll
    for (int r = 0; r < 4; r++) {
        int idx = r * 256 + tid;
        int m = idx >> 3, k4 = (idx & 7) * 4;
        pa[r] = make_float4(0.f, 0.f, 0.f, 0.f);
        if (k4 < K)
            pa[r] = *reinterpret_cast<const float4*>(Ap + (size_t)(m0 + m) * lda + k4);
        int k = idx >> 5, n4 = (idx & 31) * 4;
        pb[r] = make_float4(0.f, 0.f, 0.f, 0.f);
        if (k < K && n0 + n4 < N)
            pb[r] = *reinterpret_cast<const float4*>(Bp + (size_t)k * ldb + n0 + n4);
    }
    #pragma unroll
    for (int r = 0; r < 4; r++) {
        int idx = r * 256 + tid;
        int m = idx >> 3, k4 = (idx & 7) * 4;
        *reinterpret_cast<float4*>(&Asm[m * 36 + k4]) = pa[r];
        int k = idx >> 5, n4 = (idx & 31) * 4;
        *reinterpret_cast<float4*>(&Bsm[k * 136 + n4]) = pb[r];
    }
    __syncthreads();

    float c[4][4][4] = {};

    for (int k0 = 0; k0 < K; k0 += 32) {
        const bool nxt = (k0 + 32) < K;
        if (nxt) {
            int kn = k0 + 32;
            #pragma unroll
            for (int r = 0; r < 4; r++) {
                int idx = r * 256 + tid;
                int m = idx >> 3, k4 = (idx & 7) * 4;
                pa[r] = make_float4(0.f, 0.f, 0.f, 0.f);
                if (kn + k4 < K)
                    pa[r] = *reinterpret_cast<const float4*>(Ap + (size_t)(m0 + m) * lda + kn + k4);
                int k = idx >> 5, n4 = (idx & 31) * 4;
                pb[r] = make_float4(0.f, 0.f, 0.f, 0.f);
                if (kn + k < K && n0 + n4 < N)
                    pb[r] = *reinterpret_cast<const float4*>(Bp + (size_t)(kn + k) * ldb + n0 + n4);
            }
        }

        // ---- compute: 4 k-chunks of 8 ----
        #pragma unroll
        for (int kc = 0; kc < 4; kc++) {
            const int kk = kc * 8;
            unsigned ah[4][4], al[4][4];
            #pragma unroll
            for (int i = 0; i < 4; i++) {
                int r0 = mBase + i * 16 + lr;
                tf32_split2(Asm[r0 * 36 + kk + lc],           ah[i][0], al[i][0]);
                tf32_split2(Asm[(r0 + 8) * 36 + kk + lc],     ah[i][1], al[i][1]);
                tf32_split2(Asm[r0 * 36 + kk + lc + 4],       ah[i][2], al[i][2]);
                tf32_split2(Asm[(r0 + 8) * 36 + kk + lc + 4], ah[i][3], al[i][3]);
            }
            #pragma unroll
            for (int j = 0; j < 4; j++) {
                int cN = nBase + j * 8 + lr;
                unsigned bh[2], bl[2];
                tf32_split2(Bsm[(kk + lc) * 136 + cN],     bh[0], bl[0]);
                tf32_split2(Bsm[(kk + lc + 4) * 136 + cN], bh[1], bl[1]);
                #pragma unroll
                for (int i = 0; i < 4; i++) {
                    MMA_TF32(c[i][j], al[i], bh);
                    MMA_TF32(c[i][j], ah[i], bl);
                    MMA_TF32(c[i][j], ah[i], bh);
                }
            }
        }

        if (nxt) {
            __syncthreads();            // all warps done reading current tile
            #pragma unroll
            for (int r = 0; r < 4; r++) {
                int idx = r * 256 + tid;
                int m = idx >> 3, k4 = (idx & 7) * 4;
                *reinterpret_cast<float4*>(&Asm[m * 36 + k4]) = pa[r];
                int k = idx >> 5, n4 = (idx & 31) * 4;
                *reinterpret_cast<float4*>(&Bsm[k * 136 + n4]) = pb[r];
            }
            __syncthreads();            // stores visible
        }
    }

    // ---- epilogue ----
    #pragma unroll
    for (int i = 0; i < 4; i++) {
        int row = m0 + mBase + i * 16 + lr;
        #pragma unroll
        for (int j = 0; j < 4; j++) {
            int col = n0 + nBase + j * 8 + lc * 2;
            if (col < N) {
                #pragma unroll
                for (int h = 0; h < 2; h++) {
                    int rr = row + h * 8;
                    float v0 = alpha * c[i][j][h * 2 + 0];
                    float v1 = alpha * c[i][j][h * 2 + 1];
                    if (bias) { v0 += bias[col]; v1 += bias[col + 1]; }
                    if (act == ACT_GELU) { v0 = gelu_exact(v0); v1 = gelu_exact(v1); }
                    float* p = Cp + (size_t)rr * ldc + col;
                    if (BETA1) { p[0] += v0; p[1] += v1; }
                    else       { p[0] = v0;  p[1] = v1; }
                }
            }
        }
    }
}

// ---------------- gates: sigmoid(gh[2048,1280] @ W2[1280,3] + b2), warp/dot ---
__global__ void gates_kernel(const float* __restrict__ gh, const float* __restrict__ W2,
                             const float* __restrict__ b2, float* __restrict__ gates)
{
    int w    = (blockIdx.x * blockDim.x + threadIdx.x) >> 5;
    int lane = threadIdx.x & 31;
    if (w >= ROWS * 3) return;
    int row = w / 3, j = w % 3;
    const float* g = gh + (size_t)row * (Dm / 2);
    float acc = 0.f;
    for (int c = lane; c < Dm / 2; c += 32) acc = fmaf(g[c], W2[c * 3 + j], acc);
    #pragma unroll
    for (int o = 16; o > 0; o >>= 1) acc += __shfl_xor_sync(0xffffffffu, acc, o);
    if (lane == 0) gates[w] = 1.f / (1.f + expf(-(acc + b2[j])));
}

// ---------------- gather k/v blocks (+pos) into tb[4096, 2560] ---------------
__global__ void comp_gather(const float* __restrict__ k, const float* __restrict__ v,
                            const float* __restrict__ pos, float* __restrict__ tb)
{
    int r = blockIdx.x;                 // 0..4095
    const float* src = (r < 2048) ? k : v;
    int rr  = r & 2047;
    int b   = rr >> 10;
    int h   = (rr >> 5) & 31;
    int blk = rr & 31;
    for (int c = threadIdx.x; c < Dm; c += blockDim.x) {
        int i = c / HD, d = c % HD;
        int s = blk * BS + i;
        tb[(size_t)r * Dm + c] =
            src[((size_t)(b * Ss + s)) * Dm + h * HD + d] + pos[c];
    }
}

// ---------------- compressed-attention branch: combined = g0 * out_c ---------
__global__ void outc_kernel(const float* __restrict__ q, const float* __restrict__ kcvc,
                            const float* __restrict__ gates, float* __restrict__ combined)
{
    int idx = blockIdx.x * blockDim.x + threadIdx.x;
    if (idx >= BH * Ss) return;
    int bh = idx >> 10;
    int s  = idx & 1023;
    int b  = bh >> 5, h = bh & 31;
    const float* qrow = q + ((size_t)(b * Ss + s)) * Dm + h * HD;
    const float* kc   = kcvc + (size_t)bh * NBLK * HD;
    const float* vc   = kcvc + (size_t)2048 * HD + (size_t)bh * NBLK * HD;

    float logit[NBLK];
    float mx = -INFINITY;
    #pragma unroll
    for (int j = 0; j < NBLK; j++) {
        float acc = 0.f;
        const float* kr = kc + j * HD;
        for (int d = 0; d < HD; d++) acc = fmaf(qrow[d], kr[d], acc);
        acc *= SCALE;
        logit[j] = acc;
        mx = fmaxf(mx, acc);
    }
    float Z = 0.f;
    #pragma unroll
    for (int j = 0; j < NBLK; j++) { logit[j] = expf(logit[j] - mx); Z += logit[j]; }
    float g0 = gates[(b * Ss + s) * 3 + 0];
    float c0 = g0 / Z;
    float* out = combined + ((size_t)(b * Ss + s)) * Dm + h * HD;
    for (int d = 0; d < HD; d++) {
        float acc = 0.f;
        #pragma unroll
        for (int j = 0; j < NBLK; j++) acc = fmaf(logit[j], vc[j * HD + d], acc);
        out[d] = c0 * acc;
    }
}

// ---------------- block means + top-16 -> 32-bit block mask ------------------
__global__ void mask_kernel(const float* __restrict__ scores, unsigned* __restrict__ mask)
{
    int gw   = (blockIdx.x * blockDim.x + threadIdx.x) >> 5;
    int lane = threadIdx.x & 31;
    if (gw >= BH * Ss) return;
    const float* row = scores + (size_t)gw * Ss;
    float s = 0.f;
    for (int t = 0; t < BS; t++) s += row[lane * BS + t];

    unsigned m = 0;
    float val = s;
    for (int it = 0; it < KTOP; it++) {
        float bv = val; int bi = lane;
        #pragma unroll
        for (int off = 16; off > 0; off >>= 1) {
            float ov = __shfl_xor_sync(0xffffffffu, bv, off);
            int   oi = __shfl_xor_sync(0xffffffffu, bi, off);
            if (ov > bv || (ov == bv && oi < bi)) { bv = ov; bi = oi; }
        }
        m |= (1u << bi);
        if (lane == bi) val = -INFINITY;
    }
    if (lane == 0) mask[gw] = m;
}

// ---------------- fused dual softmax -> combined key weights (in-place) ------
__global__ void weights_kernel(float* __restrict__ scores, const unsigned* __restrict__ mask,
                               const float* __restrict__ gates)
{
    int row = blockIdx.x;               // bh*1024 + s
    int bh  = row >> 10;
    int s   = row & 1023;
    int b   = bh >> 5;
    __shared__ float sm[Ss];
    __shared__ float red[256];
    float* rp = scores + (size_t)row * Ss;
    unsigned msk = mask[row];
    int tid = threadIdx.x;

    float lmw = -INFINITY;
    for (int c = tid; c < Ss; c += 256) {
        float x = rp[c];
        sm[c] = x;
        lmw = fmaxf(lmw, x);
    }
    red[tid] = lmw; __syncthreads();
    for (int st = 128; st > 0; st >>= 1) {
        if (tid < st) red[tid] = fmaxf(red[tid], red[tid + st]);
        __syncthreads();
    }
    float mw = red[0]; __syncthreads();

    float lzw = 0.f, lzs = 0.f;
    for (int c = tid; c < Ss; c += 256) {
        float ew = expf(sm[c] - mw);
        sm[c] = ew;
        lzw += ew;
        if ((msk >> (c >> 5)) & 1u) lzs += ew;
    }
    red[tid] = lzw; __syncthreads();
    for (int st = 128; st > 0; st >>= 1) {
        if (tid < st) red[tid] += red[tid + st];
        __syncthreads();
    }
    float Zw = red[0]; __syncthreads();
    red[tid] = lzs; __syncthreads();
    for (int st = 128; st > 0; st >>= 1) {
        if (tid < st) red[tid] += red[tid + st];
        __syncthreads();
    }
    float Zs = red[0]; __syncthreads();

    float g1 = gates[(b * Ss + s) * 3 + 1];
    float g2 = gates[(b * Ss + s) * 3 + 2];
    float cw = g2 / Zw;
    float cs = g1 / Zs;
    for (int c = tid; c < Ss; c += 256) {
        float ew = sm[c];
        float w = cw * ew;
        if ((msk >> (c >> 5)) & 1u) w += cs * ew;
        rp[c] = w;
    }
}

// ---------------- host launch ------------------------------------------------
static void* symaddr(const void* sym) {
    void* p = nullptr;
    cudaGetSymbolAddress(&p, sym);
    return p;
}

extern "C" void kernel_launch(void* const* d_in, const int* in_sizes, int n_in,
                              void* d_out, int out_size)
{
    const float* hidden  = (const float*)d_in[0];
    const float* Wq      = (const float*)d_in[1];
    const float* bq      = (const float*)d_in[2];
    const float* Wk      = (const float*)d_in[3];
    const float* bk      = (const float*)d_in[4];
    const float* Wv      = (const float*)d_in[5];
    const float* bv      = (const float*)d_in[6];
    const float* Wo      = (const float*)d_in[7];
    const float* bo      = (const float*)d_in[8];
    const float* cpos    = (const float*)d_in[9];
    const float* cW1     = (const float*)d_in[10];
    const float* cb1     = (const float*)d_in[11];
    const float* cW2     = (const float*)d_in[12];
    const float* cb2     = (const float*)d_in[13];
    const float* gW1     = (const float*)d_in[14];
    const float* gb1     = (const float*)d_in[15];
    const float* gW2     = (const float*)d_in[16];
    const float* gb2     = (const float*)d_in[17];
    float* out = (float*)d_out;

    float*    q     = (float*)symaddr(g_q);
    float*    k     = (float*)symaddr(g_k);
    float*    v     = (float*)symaddr(g_v);
    float*    gh    = (float*)symaddr(g_gh);
    float*    gates = (float*)symaddr(g_gates);
    float*    tb    = (float*)symaddr(g_tb);
    float*    h1    = (float*)symaddr(g_h1);
    float*    kcvc  = (float*)symaddr(g_kcvc);
    float*    sc    = (float*)symaddr(g_scores);
    unsigned* msk   = (unsigned*)symaddr(g_mask);
    float*    comb  = (float*)symaddr(g_comb);

    dim3 blk2(16, 16);
    const long long sQh = HD;                           // per-z (head) offset
    const long long sQb = (long long)Ss * Dm - 32 * HD; // per-batch extra

    // --- top-k-critical path: sequential-k fp32 numerics (bit-identical) ---
    gemm_f32_v2<<<dim3(Dm / 128, ROWS / 128), 256>>>(hidden, Wq, bq, q, ROWS, Dm, Dm, ACT_NONE);
    gemm_f32_v2<<<dim3(Dm / 128, ROWS / 128), 256>>>(hidden, Wk, bk, k, ROWS, Dm, Dm, ACT_NONE);

    // --- smooth paths: tensor-core 3xTF32 (pipelined) ---
    mma_gemm<false><<<dim3(Dm/128, ROWS/128, 1), 256>>>(
        hidden, Wv, bv, v, ROWS, Dm, Dm, Dm, Dm, Dm, 0,0,0,0,0,0, 1.f, ACT_NONE);
    mma_gemm<false><<<dim3((Dm/2)/128, ROWS/128, 1), 256>>>(
        hidden, gW1, gb1, gh, ROWS, Dm/2, Dm, Dm, Dm/2, Dm/2, 0,0,0,0,0,0, 1.f, ACT_GELU);
    gates_kernel<<<(ROWS * 3 * 32 + 255) / 256, 256>>>(gh, gW2, gb2, gates);

    // compression MLP (k and v batched together)
    comp_gather<<<2 * BH * NBLK, 256>>>(k, v, cpos, tb);
    mma_gemm<false><<<dim3((320+127)/128, (2*BH*NBLK)/128, 1), 256>>>(
        tb, cW1, cb1, h1, 2*BH*NBLK, 320, Dm, Dm, 320, 320, 0,0,0,0,0,0, 1.f, ACT_GELU);
    mma_gemm<false><<<dim3(1, (2*BH*NBLK)/128, 1), 256>>>(
        h1, cW2, cb2, kcvc, 2*BH*NBLK, HD, 320, 320, HD, HD, 0,0,0,0,0,0, 1.f, ACT_NONE);

    // compressed branch -> combined = g0 * out_c
    outc_kernel<<<(BH * Ss) / 256, 256>>>(q, kcvc, gates, comb);

    // --- dense scores + mask: round-1 SIMT fp32 numerics (validated) ---
    scores_kernel<<<dim3(Ss / 64, Ss / 64, BH), blk2>>>(q, k, sc);
    mask_kernel<<<(BH * Ss * 32) / 256, 256>>>(sc, msk);
    weights_kernel<<<BH * Ss, 256>>>(sc, msk, gates);

    // PV (batched NN, accumulate into comb) — smooth, tensor-core
    mma_gemm<true><<<dim3(1, Ss/128, BH), 256>>>(
        sc, v, nullptr, comb, Ss, HD, Ss, Ss, Dm, Dm,
        (long long)Ss*Ss, 0, sQh, sQb, sQh, sQb, 1.f, ACT_NONE);

    // output projection — smooth, tensor-core
    mma_gemm<false><<<dim3(Dm/128, ROWS/128, 1), 256>>>(
        comb, Wo, bo, out, ROWS, Dm, Dm, Dm, Dm, Dm, 0,0,0,0,0,0, 1.f, ACT_NONE);
}

// round 9
// speedup vs baseline: 1.2563x; 1.2563x over previous
#include <cuda_runtime.h>
#include <cuda_bf16.h>
#include <math.h>

// ---------------- problem constants ----------------
#define Bb   2
#define Ss   1024
#define Dm   2560
#define Hh   32
#define HD   80
#define BS   32
#define NBLK 32
#define KTOP 16
#define BH   (Bb*Hh)          // 64
#define ROWS (Bb*Ss)          // 2048
#define SCALE 0.11180339887498949f   // 80^-0.5

#define ACT_NONE 0
#define ACT_GELU 1

// ---------------- scratch (static device globals; no allocations) ------------
__device__ float    g_q[ROWS*Dm];
__device__ float    g_k[ROWS*Dm];
__device__ float    g_v[ROWS*Dm];
__device__ float    g_gh[ROWS*(Dm/2)];
__device__ float    g_gates[ROWS*3];
__device__ float    g_tb[2*BH*NBLK*Dm];        // [4096, 2560]
__device__ float    g_h1[2*BH*NBLK*320];       // [4096, 320]
__device__ float    g_kcvc[2*BH*NBLK*HD];      // kc rows 0..2047, vc rows 2048..4095
__device__ float    g_scores[(size_t)BH*Ss*Ss];// 268 MB
__device__ unsigned g_mask[BH*Ss];
__device__ float    g_comb[ROWS*Dm];

__device__ __forceinline__ float gelu_exact(float x) {
    return 0.5f * x * (1.0f + erff(x * 0.70710678118654752440f));
}

// =====================================================================
// SIMT fp32 GEMM (Wq, Wk) — round-7 form (validated bit-identical).
// Single fmaf chain over ascending k. M%128==0, N%128==0, K%16==0.
// =====================================================================
__global__ void __launch_bounds__(256, 2)
gemm_f32_v2(const float* __restrict__ A, const float* __restrict__ B,
            const float* __restrict__ bias, float* __restrict__ C,
            int M, int N, int K, int act)
{
    __shared__ float As[16][132];   // [k][m]
    __shared__ float Bs[16][132];   // [k][n]
    const int tid = threadIdx.x;
    const int tx = tid & 15, ty = tid >> 4;
    const int m0 = blockIdx.y * 128, n0 = blockIdx.x * 128;

    float acc[8][8] = {};

    for (int k0 = 0; k0 < K; k0 += 16) {
        #pragma unroll
        for (int r = 0; r < 2; r++) {
            int idx = r * 256 + tid;
            int m = idx >> 2, k4 = (idx & 3) * 4;
            float4 f = *reinterpret_cast<const float4*>(&A[(size_t)(m0 + m) * K + k0 + k4]);
            As[k4 + 0][m] = f.x;
            As[k4 + 1][m] = f.y;
            As[k4 + 2][m] = f.z;
            As[k4 + 3][m] = f.w;
        }
        #pragma unroll
        for (int r = 0; r < 2; r++) {
            int idx = r * 256 + tid;
            int k = idx >> 5, n4 = (idx & 31) * 4;
            float4 f = *reinterpret_cast<const float4*>(&B[(size_t)(k0 + k) * N + n0 + n4]);
            *reinterpret_cast<float4*>(&Bs[k][n4]) = f;
        }
        __syncthreads();

        #pragma unroll
        for (int kk = 0; kk < 16; kk++) {
            float a[8], b[8];
            *reinterpret_cast<float4*>(&a[0]) = *reinterpret_cast<const float4*>(&As[kk][ty * 4]);
            *reinterpret_cast<float4*>(&a[4]) = *reinterpret_cast<const float4*>(&As[kk][64 + ty * 4]);
            *reinterpret_cast<float4*>(&b[0]) = *reinterpret_cast<const float4*>(&Bs[kk][tx * 4]);
            *reinterpret_cast<float4*>(&b[4]) = *reinterpret_cast<const float4*>(&Bs[kk][64 + tx * 4]);
            #pragma unroll
            for (int i = 0; i < 8; i++)
                #pragma unroll
                for (int j = 0; j < 8; j++)
                    acc[i][j] = fmaf(a[i], b[j], acc[i][j]);
        }
        __syncthreads();
    }

    #pragma unroll
    for (int i = 0; i < 8; i++) {
        int row = m0 + ((i < 4) ? (ty * 4 + i) : (64 + ty * 4 + i - 4));
        #pragma unroll
        for (int jg = 0; jg < 2; jg++) {
            int col = n0 + jg * 64 + tx * 4;
            float4 o;
            float* oc = &o.x;
            #pragma unroll
            for (int jj = 0; jj < 4; jj++) {
                float v = acc[i][jg * 4 + jj] + bias[col + jj];
                if (act == ACT_GELU) v = gelu_exact(v);
                oc[jj] = v;
            }
            *reinterpret_cast<float4*>(&C[(size_t)row * N + col]) = o;
        }
    }
}

// ---------------- ROUND-1 batched NT GEMM: scores = SCALE * Q Kᵀ -------------
__global__ void scores_kernel(const float* __restrict__ q, const float* __restrict__ k,
                              float* __restrict__ scores)
{
    int bh = blockIdx.z;
    int b = bh >> 5, h = bh & 31;
    int i0 = blockIdx.y * 64, j0 = blockIdx.x * 64;
    __shared__ float Qs[64][81];
    __shared__ float Ks[64][81];
    int tx = threadIdx.x, ty = threadIdx.y, tid = ty * 16 + tx;

    for (int e = tid; e < 64 * 80; e += 256) {
        int r = e / 80, c = e % 80;
        Qs[r][c] = q[((size_t)(b * Ss + i0 + r)) * Dm + h * HD + c];
        Ks[r][c] = k[((size_t)(b * Ss + j0 + r)) * Dm + h * HD + c];
    }
    __syncthreads();

    float acc[4][4] = {};
    #pragma unroll 8
    for (int kk = 0; kk < 80; kk++) {
        float a[4], bb[4];
        #pragma unroll
        for (int i = 0; i < 4; i++) a[i] = Qs[ty * 4 + i][kk];
        #pragma unroll
        for (int j = 0; j < 4; j++) bb[j] = Ks[tx * 4 + j][kk];
        #pragma unroll
        for (int i = 0; i < 4; i++)
            #pragma unroll
            for (int j = 0; j < 4; j++)
                acc[i][j] = fmaf(a[i], bb[j], acc[i][j]);
    }
    #pragma unroll
    for (int i = 0; i < 4; i++)
        #pragma unroll
        for (int j = 0; j < 4; j++)
            scores[((size_t)bh * Ss + i0 + ty * 4 + i) * Ss + j0 + tx * 4 + j] =
                acc[i][j] * SCALE;
}

// =====================================================================
// bf16x2 tensor-core GEMM (smooth paths, NN only):
//   C = act(alpha * A@B + bias) [+ Cprev]
//   x = hi_bf16 + lo_bf16; products hh + hl + lh via m16n8k16 bf16 MMA
//   (per-product error ~2^-17 -> safe for all smooth consumers).
//   hi/lo split ONCE at STS time into packed conflict-free planes:
//     Ahi/Alo: [m][k2] stride 20 (u32 = bf16 pair along k)
//     Bhi/Blo: [k2][n] stride 136
//   Inner loop: pure scalar LDS + MMA (zero ALU), 96 MMAs/tile.
//   block tile 128x128, BK=32, 8 warps, warp tile 64x32.
//   Requires M%128==0, K%32==0; N edge-guarded.
// =====================================================================
__device__ __forceinline__ void split_pack(float x, float y, unsigned& hi, unsigned& lo) {
    __nv_bfloat16 hx = __float2bfloat16(x);
    __nv_bfloat16 hy = __float2bfloat16(y);
    float rx = x - __bfloat162float(hx);
    float ry = y - __bfloat162float(hy);
    __nv_bfloat162 h = __halves2bfloat162(hx, hy);
    __nv_bfloat162 l = __halves2bfloat162(__float2bfloat16(rx), __float2bfloat16(ry));
    hi = *reinterpret_cast<unsigned*>(&h);
    lo = *reinterpret_cast<unsigned*>(&l);
}

#define MMA_BF16(C, Ar, Br)                                              \
    asm volatile(                                                        \
        "mma.sync.aligned.m16n8k16.row.col.f32.bf16.bf16.f32 "           \
        "{%0,%1,%2,%3},{%4,%5,%6,%7},{%8,%9},{%0,%1,%2,%3};"             \
        : "+f"(C[0]), "+f"(C[1]), "+f"(C[2]), "+f"(C[3])                 \
        : "r"(Ar[0]), "r"(Ar[1]), "r"(Ar[2]), "r"(Ar[3]),                \
          "r"(Br[0]), "r"(Br[1]))

template<bool BETA1>
__global__ void __launch_bounds__(256)
mma_gemm(const float* __restrict__ A, const float* __restrict__ B,
         const float* __restrict__ bias, float* __restrict__ C,
         int M, int N, int K, int lda, int ldb, int ldc,
         long long sAz, long long sAb, long long sBz, long long sBb,
         long long sCz, long long sCb, float alpha, int act)
{
    __shared__ unsigned Ahi[128 * 20], Alo[128 * 20];   // [m][k2], 10KB each
    __shared__ unsigned Bhi[16 * 136], Blo[16 * 136];   // [k2][n], 8.7KB each

    const int z = blockIdx.z;
    const float* Ap = A + (size_t)z * sAz + (size_t)(z >> 5) * sAb;
    const float* Bp = B + (size_t)z * sBz + (size_t)(z >> 5) * sBb;
    float*       Cp = C + (size_t)z * sCz + (size_t)(z >> 5) * sCb;

    const int m0 = blockIdx.y * 128, n0 = blockIdx.x * 128;
    const int tid  = threadIdx.x;
    const int warp = tid >> 5, lane = tid & 31;
    const int wm = warp & 1, wn = warp >> 1;          // 2 x 4 warps
    const int mBase = wm * 64, nBase = wn * 32;
    const int lr = lane >> 2, lc = lane & 3;

    float c[4][4][4] = {};

    for (int k0 = 0; k0 < K; k0 += 32) {
        // ---- A tile 128x32 -> split+pack to Ahi/Alo[m][k2] ----
        #pragma unroll
        for (int r = 0; r < 4; r++) {
            int idx = r * 256 + tid;
            int m = idx >> 3, k4 = (idx & 7) * 4;
            float4 f = *reinterpret_cast<const float4*>(Ap + (size_t)(m0 + m) * lda + k0 + k4);
            unsigned h0, l0, h1, l1;
            split_pack(f.x, f.y, h0, l0);
            split_pack(f.z, f.w, h1, l1);
            int ad = m * 20 + (k4 >> 1);
            *reinterpret_cast<uint2*>(&Ahi[ad]) = make_uint2(h0, h1);
            *reinterpret_cast<uint2*>(&Alo[ad]) = make_uint2(l0, l1);
        }
        // ---- B tile 32x128 -> split+pack (pairs along k) to Bhi/Blo[k2][n] ----
        #pragma unroll
        for (int r = 0; r < 2; r++) {
            int idx = r * 256 + tid;
            int k2 = idx >> 5, n4 = (idx & 31) * 4;
            float4 f0 = make_float4(0.f, 0.f, 0.f, 0.f);
            float4 f1 = make_float4(0.f, 0.f, 0.f, 0.f);
            if (n0 + n4 < N) {
                f0 = *reinterpret_cast<const float4*>(Bp + (size_t)(k0 + 2 * k2) * ldb + n0 + n4);
                f1 = *reinterpret_cast<const float4*>(Bp + (size_t)(k0 + 2 * k2 + 1) * ldb + n0 + n4);
            }
            const float* e0 = &f0.x;
            const float* e1 = &f1.x;
            uint4 hv, lv;
            unsigned* hp = &hv.x;
            unsigned* lp = &lv.x;
            #pragma unroll
            for (int s = 0; s < 4; s++)
                split_pack(e0[s], e1[s], hp[s], lp[s]);
            int bd = k2 * 136 + n4;
            *reinterpret_cast<uint4*>(&Bhi[bd]) = hv;
            *reinterpret_cast<uint4*>(&Blo[bd]) = lv;
        }
        __syncthreads();

        // ---- 2 chunks of k=16 ----
        #pragma unroll
        for (int ch = 0; ch < 2; ch++) {
            const int kk2 = ch * 8;
            unsigned ah[4][4], al[4][4];
            #pragma unroll
            for (int i = 0; i < 4; i++) {
                int r0 = (mBase + i * 16 + lr) * 20;
                int r8 = r0 + 8 * 20;
                ah[i][0] = Ahi[r0 + kk2 + lc];
                ah[i][1] = Ahi[r8 + kk2 + lc];
                ah[i][2] = Ahi[r0 + kk2 + lc + 4];
                ah[i][3] = Ahi[r8 + kk2 + lc + 4];
                al[i][0] = Alo[r0 + kk2 + lc];
                al[i][1] = Alo[r8 + kk2 + lc];
                al[i][2] = Alo[r0 + kk2 + lc + 4];
                al[i][3] = Alo[r8 + kk2 + lc + 4];
            }
            #pragma unroll
            for (int j = 0; j < 4; j++) {
                int cN = nBase + j * 8 + lr;
                unsigned bh[2], bl[2];
                bh[0] = Bhi[(kk2 + lc) * 136 + cN];
                bh[1] = Bhi[(kk2 + 4 + lc) * 136 + cN];
                bl[0] = Blo[(kk2 + lc) * 136 + cN];
                bl[1] = Blo[(kk2 + 4 + lc) * 136 + cN];
                #pragma unroll
                for (int i = 0; i < 4; i++) {
                    MMA_BF16(c[i][j], al[i], bh);
                    MMA_BF16(c[i][j], ah[i], bl);
                    MMA_BF16(c[i][j], ah[i], bh);
                }
            }
        }
        __syncthreads();
    }

    // ---- epilogue ----
    #pragma unroll
    for (int i = 0; i < 4; i++) {
        int row = m0 + mBase + i * 16 + lr;
        #pragma unroll
        for (int j = 0; j < 4; j++) {
            int col = n0 + nBase + j * 8 + lc * 2;
            if (col < N) {
                #pragma unroll
                for (int h = 0; h < 2; h++) {
                    int rr = row + h * 8;
                    float v0 = alpha * c[i][j][h * 2 + 0];
                    float v1 = alpha * c[i][j][h * 2 + 1];
                    if (bias) { v0 += bias[col]; v1 += bias[col + 1]; }
                    if (act == ACT_GELU) { v0 = gelu_exact(v0); v1 = gelu_exact(v1); }
                    float* p = Cp + (size_t)rr * ldc + col;
                    if (BETA1) { p[0] += v0; p[1] += v1; }
                    else       { p[0] = v0;  p[1] = v1; }
                }
            }
        }
    }
}

// ---------------- gates: sigmoid(gh[2048,1280] @ W2[1280,3] + b2), warp/dot ---
__global__ void gates_kernel(const float* __restrict__ gh, const float* __restrict__ W2,
                             const float* __restrict__ b2, float* __restrict__ gates)
{
    int w    = (blockIdx.x * blockDim.x + threadIdx.x) >> 5;
    int lane = threadIdx.x & 31;
    if (w >= ROWS * 3) return;
    int row = w / 3, j = w % 3;
    const float* g = gh + (size_t)row * (Dm / 2);
    float acc = 0.f;
    for (int c = lane; c < Dm / 2; c += 32) acc = fmaf(g[c], W2[c * 3 + j], acc);
    #pragma unroll
    for (int o = 16; o > 0; o >>= 1) acc += __shfl_xor_sync(0xffffffffu, acc, o);
    if (lane == 0) gates[w] = 1.f / (1.f + expf(-(acc + b2[j])));
}

// ---------------- gather k/v blocks (+pos) into tb[4096, 2560] ---------------
__global__ void comp_gather(const float* __restrict__ k, const float* __restrict__ v,
                            const float* __restrict__ pos, float* __restrict__ tb)
{
    int r = blockIdx.x;                 // 0..4095
    const float* src = (r < 2048) ? k : v;
    int rr  = r & 2047;
    int b   = rr >> 10;
    int h   = (rr >> 5) & 31;
    int blk = rr & 31;
    for (int c = threadIdx.x; c < Dm; c += blockDim.x) {
        int i = c / HD, d = c % HD;
        int s = blk * BS + i;
        tb[(size_t)r * Dm + c] =
            src[((size_t)(b * Ss + s)) * Dm + h * HD + d] + pos[c];
    }
}

// ---------------- compressed-attention branch: combined = g0 * out_c ---------
__global__ void outc_kernel(const float* __restrict__ q, const float* __restrict__ kcvc,
                            const float* __restrict__ gates, float* __restrict__ combined)
{
    int idx = blockIdx.x * blockDim.x + threadIdx.x;
    if (idx >= BH * Ss) return;
    int bh = idx >> 10;
    int s  = idx & 1023;
    int b  = bh >> 5, h = bh & 31;
    const float* qrow = q + ((size_t)(b * Ss + s)) * Dm + h * HD;
    const float* kc   = kcvc + (size_t)bh * NBLK * HD;
    const float* vc   = kcvc + (size_t)2048 * HD + (size_t)bh * NBLK * HD;

    float logit[NBLK];
    float mx = -INFINITY;
    #pragma unroll
    for (int j = 0; j < NBLK; j++) {
        float acc = 0.f;
        const float* kr = kc + j * HD;
        for (int d = 0; d < HD; d++) acc = fmaf(qrow[d], kr[d], acc);
        acc *= SCALE;
        logit[j] = acc;
        mx = fmaxf(mx, acc);
    }
    float Z = 0.f;
    #pragma unroll
    for (int j = 0; j < NBLK; j++) { logit[j] = expf(logit[j] - mx); Z += logit[j]; }
    float g0 = gates[(b * Ss + s) * 3 + 0];
    float c0 = g0 / Z;
    float* out = combined + ((size_t)(b * Ss + s)) * Dm + h * HD;
    for (int d = 0; d < HD; d++) {
        float acc = 0.f;
        #pragma unroll
        for (int j = 0; j < NBLK; j++) acc = fmaf(logit[j], vc[j * HD + d], acc);
        out[d] = c0 * acc;
    }
}

// ---------------- block means + top-16 -> 32-bit block mask ------------------
__global__ void mask_kernel(const float* __restrict__ scores, unsigned* __restrict__ mask)
{
    int gw   = (blockIdx.x * blockDim.x + threadIdx.x) >> 5;
    int lane = threadIdx.x & 31;
    if (gw >= BH * Ss) return;
    const float* row = scores + (size_t)gw * Ss;
    float s = 0.f;
    for (int t = 0; t < BS; t++) s += row[lane * BS + t];

    unsigned m = 0;
    float val = s;
    for (int it = 0; it < KTOP; it++) {
        float bv = val; int bi = lane;
        #pragma unroll
        for (int off = 16; off > 0; off >>= 1) {
            float ov = __shfl_xor_sync(0xffffffffu, bv, off);
            int   oi = __shfl_xor_sync(0xffffffffu, bi, off);
            if (ov > bv || (ov == bv && oi < bi)) { bv = ov; bi = oi; }
        }
        m |= (1u << bi);
        if (lane == bi) val = -INFINITY;
    }
    if (lane == 0) mask[gw] = m;
}

// ---------------- fused dual softmax -> combined key weights (in-place) ------
__global__ void weights_kernel(float* __restrict__ scores, const unsigned* __restrict__ mask,
                               const float* __restrict__ gates)
{
    int row = blockIdx.x;               // bh*1024 + s
    int bh  = row >> 10;
    int s   = row & 1023;
    int b   = bh >> 5;
    __shared__ float sm[Ss];
    __shared__ float red[256];
    float* rp = scores + (size_t)row * Ss;
    unsigned msk = mask[row];
    int tid = threadIdx.x;

    float lmw = -INFINITY;
    for (int c = tid; c < Ss; c += 256) {
        float x = rp[c];
        sm[c] = x;
        lmw = fmaxf(lmw, x);
    }
    red[tid] = lmw; __syncthreads();
    for (int st = 128; st > 0; st >>= 1) {
        if (tid < st) red[tid] = fmaxf(red[tid], red[tid + st]);
        __syncthreads();
    }
    float mw = red[0]; __syncthreads();

    float lzw = 0.f, lzs = 0.f;
    for (int c = tid; c < Ss; c += 256) {
        float ew = expf(sm[c] - mw);
        sm[c] = ew;
        lzw += ew;
        if ((msk >> (c >> 5)) & 1u) lzs += ew;
    }
    red[tid] = lzw; __syncthreads();
    for (int st = 128; st > 0; st >>= 1) {
        if (tid < st) red[tid] += red[tid + st];
        __syncthreads();
    }
    float Zw = red[0]; __syncthreads();
    red[tid] = lzs; __syncthreads();
    for (int st = 128; st > 0; st >>= 1) {
        if (tid < st) red[tid] += red[tid + st];
        __syncthreads();
    }
    float Zs = red[0]; __syncthreads();

    float g1 = gates[(b * Ss + s) * 3 + 1];
    float g2 = gates[(b * Ss + s) * 3 + 2];
    float cw = g2 / Zw;
    float cs = g1 / Zs;
    for (int c = tid; c < Ss; c += 256) {
        float ew = sm[c];
        float w = cw * ew;
        if ((msk >> (c >> 5)) & 1u) w += cs * ew;
        rp[c] = w;
    }
}

// ---------------- host launch ------------------------------------------------
static void* symaddr(const void* sym) {
    void* p = nullptr;
    cudaGetSymbolAddress(&p, sym);
    return p;
}

extern "C" void kernel_launch(void* const* d_in, const int* in_sizes, int n_in,
                              void* d_out, int out_size)
{
    const float* hidden  = (const float*)d_in[0];
    const float* Wq      = (const float*)d_in[1];
    const float* bq      = (const float*)d_in[2];
    const float* Wk      = (const float*)d_in[3];
    const float* bk      = (const float*)d_in[4];
    const float* Wv      = (const float*)d_in[5];
    const float* bv      = (const float*)d_in[6];
    const float* Wo      = (const float*)d_in[7];
    const float* bo      = (const float*)d_in[8];
    const float* cpos    = (const float*)d_in[9];
    const float* cW1     = (const float*)d_in[10];
    const float* cb1     = (const float*)d_in[11];
    const float* cW2     = (const float*)d_in[12];
    const float* cb2     = (const float*)d_in[13];
    const float* gW1     = (const float*)d_in[14];
    const float* gb1     = (const float*)d_in[15];
    const float* gW2     = (const float*)d_in[16];
    const float* gb2     = (const float*)d_in[17];
    float* out = (float*)d_out;

    float*    q     = (float*)symaddr(g_q);
    float*    k     = (float*)symaddr(g_k);
    float*    v     = (float*)symaddr(g_v);
    float*    gh    = (float*)symaddr(g_gh);
    float*    gates = (float*)symaddr(g_gates);
    float*    tb    = (float*)symaddr(g_tb);
    float*    h1    = (float*)symaddr(g_h1);
    float*    kcvc  = (float*)symaddr(g_kcvc);
    float*    sc    = (float*)symaddr(g_scores);
    unsigned* msk   = (unsigned*)symaddr(g_mask);
    float*    comb  = (float*)symaddr(g_comb);

    dim3 blk2(16, 16);
    const long long sQh = HD;                           // per-z (head) offset
    const long long sQb = (long long)Ss * Dm - 32 * HD; // per-batch extra

    // --- top-k-critical path: sequential-k fp32 numerics (bit-identical) ---
    gemm_f32_v2<<<dim3(Dm / 128, ROWS / 128), 256>>>(hidden, Wq, bq, q, ROWS, Dm, Dm, ACT_NONE);
    gemm_f32_v2<<<dim3(Dm / 128, ROWS / 128), 256>>>(hidden, Wk, bk, k, ROWS, Dm, Dm, ACT_NONE);

    // --- smooth paths: tensor-core bf16x2 ---
    mma_gemm<false><<<dim3(Dm/128, ROWS/128, 1), 256>>>(
        hidden, Wv, bv, v, ROWS, Dm, Dm, Dm, Dm, Dm, 0,0,0,0,0,0, 1.f, ACT_NONE);
    mma_gemm<false><<<dim3((Dm/2)/128, ROWS/128, 1), 256>>>(
        hidden, gW1, gb1, gh, ROWS, Dm/2, Dm, Dm, Dm/2, Dm/2, 0,0,0,0,0,0, 1.f, ACT_GELU);
    gates_kernel<<<(ROWS * 3 * 32 + 255) / 256, 256>>>(gh, gW2, gb2, gates);

    // compression MLP (k and v batched together)
    comp_gather<<<2 * BH * NBLK, 256>>>(k, v, cpos, tb);
    mma_gemm<false><<<dim3((320+127)/128, (2*BH*NBLK)/128, 1), 256>>>(
        tb, cW1, cb1, h1, 2*BH*NBLK, 320, Dm, Dm, 320, 320, 0,0,0,0,0,0, 1.f, ACT_GELU);
    mma_gemm<false><<<dim3(1, (2*BH*NBLK)/128, 1), 256>>>(
        h1, cW2, cb2, kcvc, 2*BH*NBLK, HD, 320, 320, HD, HD, 0,0,0,0,0,0, 1.f, ACT_NONE);

    // compressed branch -> combined = g0 * out_c
    outc_kernel<<<(BH * Ss) / 256, 256>>>(q, kcvc, gates, comb);

    // --- dense scores + mask: round-1 SIMT fp32 numerics (validated) ---
    scores_kernel<<<dim3(Ss / 64, Ss / 64, BH), blk2>>>(q, k, sc);
    mask_kernel<<<(BH * Ss * 32) / 256, 256>>>(sc, msk);
    weights_kernel<<<BH * Ss, 256>>>(sc, msk, gates);

    // PV (batched NN, accumulate into comb) — smooth, tensor-core
    mma_gemm<true><<<dim3(1, Ss/128, BH), 256>>>(
        sc, v, nullptr, comb, Ss, HD, Ss, Ss, Dm, Dm,
        (long long)Ss*Ss, 0, sQh, sQb, sQh, sQb, 1.f, ACT_NONE);

    // output projection — smooth, tensor-core
    mma_gemm<false><<<dim3(Dm/128, ROWS/128, 1), 256>>>(
        comb, Wo, bo, out, ROWS, Dm, Dm, Dm, Dm, Dm, 0,0,0,0,0,0, 1.f, ACT_NONE);
}